// round 6
// baseline (speedup 1.0000x reference)
#include <cuda_runtime.h>
#include <cuda_bf16.h>
#include <cstdint>

// ---------------- problem constants ----------------
#define BATCH   2048
#define NATOM   96
#define NIN     128
#define NHID    64
#define SHIFTC  0.6931471805599453f

// ---------------- precomputed W1 hi/lo packed image (B-fragment layout) ----------------
// uint4 index = (nt*8 + kt)*32 + lane ; .xy = hi pair (b0,b1), .zw = lo pair (b0,b1)
__device__ __align__(16) uint4 g_wpk[2048];   // 32 KB, L1/L2-resident

// W1 is [NIN=128][NHID=64] row-major.  B fragment for mma.m16n8k16.row.col:
// lane = g*4+tg holds b0 = W[n=nt*8+g][k=kt*16+2tg+{0,1}], b1 = same n, k+8+{0,1}.
__global__ void prep_w_kernel(const float* __restrict__ W1) {
    int idx = blockIdx.x * blockDim.x + threadIdx.x;
    if (idx >= NIN * NHID) return;
    int k = idx >> 6;          // 0..127
    int n = idx & 63;          // 0..63
    float w = W1[idx];
    __nv_bfloat16 hi = __float2bfloat16_rn(w);
    __nv_bfloat16 lo = __float2bfloat16_rn(w - __bfloat162float(hi));
    int nt = n >> 3, g = n & 7;
    int kt = k >> 4, kl = k & 15;
    int tg = (kl >> 1) & 3, br = kl >> 3, odd = kl & 1;
    uint32_t base = (uint32_t)(((nt * 8 + kt) * 32 + (g * 4 + tg)) * 16);
    unsigned char* p = reinterpret_cast<unsigned char*>(g_wpk);
    *reinterpret_cast<__nv_bfloat16*>(p + base + br * 4 + odd * 2)     = hi;
    *reinterpret_cast<__nv_bfloat16*>(p + base + 8 + br * 4 + odd * 2) = lo;
}

// ---------------- device helpers ----------------
__device__ __forceinline__ void mma_bf16(float* c, const uint32_t* a, const uint32_t* b) {
    asm volatile(
        "mma.sync.aligned.m16n8k16.row.col.f32.bf16.bf16.f32 "
        "{%0,%1,%2,%3}, {%4,%5,%6,%7}, {%8,%9}, {%0,%1,%2,%3};"
        : "+f"(c[0]), "+f"(c[1]), "+f"(c[2]), "+f"(c[3])
        : "r"(a[0]), "r"(a[1]), "r"(a[2]), "r"(a[3]), "r"(b[0]), "r"(b[1]));
}

__device__ __forceinline__ float ssp(float z) {
    // shifted softplus, numerically stable
    return fmaxf(z, 0.f) + __logf(1.f + __expf(-fabsf(z))) - SHIFTC;
}

// hi/lo bf16 split of a float2 into packed bf16x2 registers
__device__ __forceinline__ void split2(float2 v, uint32_t& hi, uint32_t& lo) {
    __nv_bfloat162 h = __floats2bfloat162_rn(v.x, v.y);
    float rx = v.x - __low2float(h);
    float ry = v.y - __high2float(h);
    __nv_bfloat162 l = __floats2bfloat162_rn(rx, ry);
    hi = *reinterpret_cast<uint32_t*>(&h);
    lo = *reinterpret_cast<uint32_t*>(&l);
}

// ---------------- main fused kernel: one CTA (3 warps) per batch sample ----------------
// Warp w owns atom rows [32w, 32w+32) as TWO m16 tiles (each B load feeds 6 MMAs).
// Register-lean variant: B fragments are loaded inline per nt (L1-resident after the
// first CTA touches them), A loads batched per kt. __launch_bounds__(96,6) caps regs
// at 113 -> 6 CTAs/SM (28% occ) vs 4 before: the R5 profile showed a latency-bound
// kernel at 16.6% occ with nothing saturated, so warps are the scarce resource.
__global__ void __launch_bounds__(96, 6)
atomwise_kernel(const float* __restrict__ rep,
                const int*   __restrict__ atomic_numbers,
                const float* __restrict__ atom_mask,
                const float* __restrict__ b1,
                const float* __restrict__ W2,
                const float* __restrict__ b2,
                const float* __restrict__ atomref,
                const float* __restrict__ mean,
                const float* __restrict__ stddev,
                float*       __restrict__ out) {
    __shared__ float red[4];

    const int tid  = threadIdx.x;
    const int w    = tid >> 5;          // warp 0..2
    const int lane = tid & 31;
    const int b    = blockIdx.x;

    const int qr = lane >> 2;           // 0..7 (row group)
    const int qc = lane & 3;            // 0..3 (col group)
    const int r0 = w * 32 + qr;         // rows r0, r0+8 (m-tile 0); r0+16, r0+24 (m-tile 1)

    const float* xb = rep + (size_t)b * (NATOM * NIN);
    const float* p0 = xb + (r0     ) * NIN + qc * 2;
    const float* p1 = xb + (r0 +  8) * NIN + qc * 2;
    const float* p2 = xb + (r0 + 16) * NIN + qc * 2;
    const float* p3 = xb + (r0 + 24) * NIN + qc * 2;

    float acc[2][8][4];
    #pragma unroll
    for (int m = 0; m < 2; m++)
        #pragma unroll
        for (int nt = 0; nt < 8; nt++)
            #pragma unroll
            for (int r = 0; r < 4; r++) acc[m][nt][r] = 0.f;

    // ---- 3-chain hi/lo bf16 HMMA: D = Xhi*Whi + Xhi*Wlo + Xlo*Whi ----
    #pragma unroll
    for (int kt = 0; kt < 8; kt++) {
        // A fragments for both m-tiles: direct fp32 loads (32B-sector aligned per quad)
        float2 x0 = __ldg(reinterpret_cast<const float2*>(p0 + kt * 16));
        float2 x1 = __ldg(reinterpret_cast<const float2*>(p1 + kt * 16));
        float2 x2 = __ldg(reinterpret_cast<const float2*>(p0 + kt * 16 + 8));
        float2 x3 = __ldg(reinterpret_cast<const float2*>(p1 + kt * 16 + 8));
        float2 y0 = __ldg(reinterpret_cast<const float2*>(p2 + kt * 16));
        float2 y1 = __ldg(reinterpret_cast<const float2*>(p3 + kt * 16));
        float2 y2 = __ldg(reinterpret_cast<const float2*>(p2 + kt * 16 + 8));
        float2 y3 = __ldg(reinterpret_cast<const float2*>(p3 + kt * 16 + 8));

        uint32_t ahi0[4], alo0[4], ahi1[4], alo1[4];
        split2(x0, ahi0[0], alo0[0]);
        split2(x1, ahi0[1], alo0[1]);
        split2(x2, ahi0[2], alo0[2]);
        split2(x3, ahi0[3], alo0[3]);
        split2(y0, ahi1[0], alo1[0]);
        split2(y1, ahi1[1], alo1[1]);
        split2(y2, ahi1[2], alo1[2]);
        split2(y3, ahi1[3], alo1[3]);

        #pragma unroll
        for (int nt = 0; nt < 8; nt++) {
            uint4 bb = __ldg(&g_wpk[(nt * 8 + kt) * 32 + lane]);  // L1-hit after warmup
            // two independent chains (m-tile 0 / m-tile 1)
            mma_bf16(acc[0][nt], ahi0, &bb.x);   // hi*hi
            mma_bf16(acc[1][nt], ahi1, &bb.x);
            mma_bf16(acc[0][nt], ahi0, &bb.z);   // hi*lo
            mma_bf16(acc[1][nt], ahi1, &bb.z);
            mma_bf16(acc[0][nt], alo0, &bb.x);   // lo*hi
            mma_bf16(acc[1][nt], alo1, &bb.x);
        }
    }

    // ---- epilogue: bias + ssp + W2 dot, quad shuffle-reduce ----
    float sum0 = 0.f, sum1 = 0.f, sum2 = 0.f, sum3 = 0.f;  // rows r0, r0+8, r0+16, r0+24
    const int tg2 = qc * 2;
    #pragma unroll
    for (int nt = 0; nt < 8; nt++) {
        int c0 = nt * 8 + tg2;
        float2 b1v = __ldg(reinterpret_cast<const float2*>(b1 + c0));
        float2 w2v = __ldg(reinterpret_cast<const float2*>(W2 + c0));
        sum0 = fmaf(ssp(acc[0][nt][0] + b1v.x), w2v.x, sum0);
        sum0 = fmaf(ssp(acc[0][nt][1] + b1v.y), w2v.y, sum0);
        sum1 = fmaf(ssp(acc[0][nt][2] + b1v.x), w2v.x, sum1);
        sum1 = fmaf(ssp(acc[0][nt][3] + b1v.y), w2v.y, sum1);
        sum2 = fmaf(ssp(acc[1][nt][0] + b1v.x), w2v.x, sum2);
        sum2 = fmaf(ssp(acc[1][nt][1] + b1v.y), w2v.y, sum2);
        sum3 = fmaf(ssp(acc[1][nt][2] + b1v.x), w2v.x, sum3);
        sum3 = fmaf(ssp(acc[1][nt][3] + b1v.y), w2v.y, sum3);
    }
    // reduce over the 4 lanes of each quad (cols)
    sum0 += __shfl_xor_sync(0xffffffffu, sum0, 1);
    sum0 += __shfl_xor_sync(0xffffffffu, sum0, 2);
    sum1 += __shfl_xor_sync(0xffffffffu, sum1, 1);
    sum1 += __shfl_xor_sync(0xffffffffu, sum1, 2);
    sum2 += __shfl_xor_sync(0xffffffffu, sum2, 1);
    sum2 += __shfl_xor_sync(0xffffffffu, sum2, 2);
    sum3 += __shfl_xor_sync(0xffffffffu, sum3, 1);
    sum3 += __shfl_xor_sync(0xffffffffu, sum3, 2);

    // per-row finish on quad leaders, then warp-sum (deterministic)
    float contrib = 0.f;
    if (qc == 0) {
        float scB2 = b2[0], scMean = mean[0], scStd = stddev[0];
        float s[4] = {sum0, sum1, sum2, sum3};
        float tot = 0.f;
        #pragma unroll
        for (int m = 0; m < 4; m++) {
            int row = r0 + m * 8;
            int g = b * NATOM + row;
            float v = (s[m] + scB2) * scStd + scMean;
            v += atomref[atomic_numbers[g]];
            v *= atom_mask[g];
            tot += v;
        }
        contrib = tot;
    }
    // nonzero only at lanes ≡ 0 (mod 4): stages 4, 8, 16 suffice
    contrib += __shfl_xor_sync(0xffffffffu, contrib, 4);
    contrib += __shfl_xor_sync(0xffffffffu, contrib, 8);
    contrib += __shfl_xor_sync(0xffffffffu, contrib, 16);

    if (lane == 0) red[w] = contrib;
    __syncthreads();
    if (tid == 0) out[b] = red[0] + red[1] + red[2];
}

// ---------------- host launch ----------------
extern "C" void kernel_launch(void* const* d_in, const int* in_sizes, int n_in,
                              void* d_out, int out_size) {
    const float* rep   = (const float*)d_in[0];
    const int*   zn    = (const int*)  d_in[1];
    const float* mask  = (const float*)d_in[2];
    const float* W1    = (const float*)d_in[3];
    const float* b1    = (const float*)d_in[4];
    const float* W2    = (const float*)d_in[5];
    const float* b2    = (const float*)d_in[6];
    const float* aref  = (const float*)d_in[7];
    const float* mean  = (const float*)d_in[8];
    const float* stdd  = (const float*)d_in[9];
    float* out = (float*)d_out;

    prep_w_kernel<<<32, 256>>>(W1);
    atomwise_kernel<<<BATCH, 96>>>(rep, zn, mask, b1, W2, b2, aref, mean, stdd, out);
}

// round 7
// speedup vs baseline: 1.3607x; 1.3607x over previous
#include <cuda_runtime.h>
#include <cuda_bf16.h>
#include <cstdint>

// ---------------- problem constants ----------------
#define BATCH   2048
#define NATOM   96
#define NIN     128
#define NHID    64
#define SHIFTC  0.6931471805599453f

// ---------------- precomputed W1 hi/lo packed image (B-fragment layout) ----------------
// uint4 index = (nt*8 + kt)*32 + lane ; .xy = hi pair (b0,b1), .zw = lo pair (b0,b1)
__device__ __align__(16) uint4 g_wpk[2048];   // 32 KB, L1/L2-resident

// W1 is [NIN=128][NHID=64] row-major.  B fragment for mma.m16n8k16.row.col:
// lane = g*4+tg holds b0 = W[n=nt*8+g][k=kt*16+2tg+{0,1}], b1 = same n, k+8+{0,1}.
__global__ void prep_w_kernel(const float* __restrict__ W1) {
    int idx = blockIdx.x * blockDim.x + threadIdx.x;
    if (idx >= NIN * NHID) return;
    int k = idx >> 6;          // 0..127
    int n = idx & 63;          // 0..63
    float w = W1[idx];
    __nv_bfloat16 hi = __float2bfloat16_rn(w);
    __nv_bfloat16 lo = __float2bfloat16_rn(w - __bfloat162float(hi));
    int nt = n >> 3, g = n & 7;
    int kt = k >> 4, kl = k & 15;
    int tg = (kl >> 1) & 3, br = kl >> 3, odd = kl & 1;
    uint32_t base = (uint32_t)(((nt * 8 + kt) * 32 + (g * 4 + tg)) * 16);
    unsigned char* p = reinterpret_cast<unsigned char*>(g_wpk);
    *reinterpret_cast<__nv_bfloat16*>(p + base + br * 4 + odd * 2)     = hi;
    *reinterpret_cast<__nv_bfloat16*>(p + base + 8 + br * 4 + odd * 2) = lo;
}

// ---------------- device helpers ----------------
__device__ __forceinline__ void mma_bf16(float* c, const uint32_t* a, const uint32_t* b) {
    asm volatile(
        "mma.sync.aligned.m16n8k16.row.col.f32.bf16.bf16.f32 "
        "{%0,%1,%2,%3}, {%4,%5,%6,%7}, {%8,%9}, {%0,%1,%2,%3};"
        : "+f"(c[0]), "+f"(c[1]), "+f"(c[2]), "+f"(c[3])
        : "r"(a[0]), "r"(a[1]), "r"(a[2]), "r"(a[3]), "r"(b[0]), "r"(b[1]));
}

__device__ __forceinline__ float ssp(float z) {
    // shifted softplus, numerically stable
    return fmaxf(z, 0.f) + __logf(1.f + __expf(-fabsf(z))) - SHIFTC;
}

// hi/lo bf16 split of a float2 into packed bf16x2 registers
__device__ __forceinline__ void split2(float2 v, uint32_t& hi, uint32_t& lo) {
    __nv_bfloat162 h = __floats2bfloat162_rn(v.x, v.y);
    float rx = v.x - __low2float(h);
    float ry = v.y - __high2float(h);
    __nv_bfloat162 l = __floats2bfloat162_rn(rx, ry);
    hi = *reinterpret_cast<uint32_t*>(&h);
    lo = *reinterpret_cast<uint32_t*>(&l);
}

// ---------------- main fused kernel: one CTA (6 warps) per batch sample ----------------
// Warp w: row-group rg = w>>1 owns atom rows [32rg, 32rg+32) (two m16 tiles);
// col-group cg = w&1 owns hidden cols [32cg, 32cg+32) (four n8 tiles).
// acc shrinks to 32 regs/thread -> natural regs ~100 -> 3 CTAs/SM = 18 warps (28% occ)
// with NO spills (R6 showed forcing 96 regs against a 168-reg tile spills).
// K is not split, so ssp(h_j) is complete per warp; col-halves of the W2 dot add
// linearly, and col-group 0 adds the per-row constant (b2*std+mean+atomref)*mask.
__global__ void __launch_bounds__(192, 3)
atomwise_kernel(const float* __restrict__ rep,
                const int*   __restrict__ atomic_numbers,
                const float* __restrict__ atom_mask,
                const float* __restrict__ b1,
                const float* __restrict__ W2,
                const float* __restrict__ b2,
                const float* __restrict__ atomref,
                const float* __restrict__ mean,
                const float* __restrict__ stddev,
                float*       __restrict__ out) {
    __shared__ float red[8];

    const int tid  = threadIdx.x;
    const int w    = tid >> 5;          // warp 0..5
    const int lane = tid & 31;
    const int b    = blockIdx.x;

    const int rg = w >> 1;              // row group 0..2
    const int cg = w & 1;               // col group 0..1

    const int qr = lane >> 2;           // 0..7 (row within tile)
    const int qc = lane & 3;            // 0..3 (col pair)
    const int r0 = rg * 32 + qr;        // rows r0, r0+8 (m-tile 0); r0+16, r0+24 (m-tile 1)

    const float* xb = rep + (size_t)b * (NATOM * NIN);
    const float* p0 = xb + (r0     ) * NIN + qc * 2;
    const float* p1 = xb + (r0 +  8) * NIN + qc * 2;
    const float* p2 = xb + (r0 + 16) * NIN + qc * 2;
    const float* p3 = xb + (r0 + 24) * NIN + qc * 2;

    float acc[2][4][4];
    #pragma unroll
    for (int m = 0; m < 2; m++)
        #pragma unroll
        for (int nt = 0; nt < 4; nt++)
            #pragma unroll
            for (int r = 0; r < 4; r++) acc[m][nt][r] = 0.f;

    // ---- 3-chain hi/lo bf16 HMMA: D = Xhi*Whi + Xhi*Wlo + Xlo*Whi ----
    #pragma unroll
    for (int kt = 0; kt < 8; kt++) {
        // A fragments for both m-tiles (col-group partners hit L1 on the repeat)
        float2 x0 = __ldg(reinterpret_cast<const float2*>(p0 + kt * 16));
        float2 x1 = __ldg(reinterpret_cast<const float2*>(p1 + kt * 16));
        float2 x2 = __ldg(reinterpret_cast<const float2*>(p0 + kt * 16 + 8));
        float2 x3 = __ldg(reinterpret_cast<const float2*>(p1 + kt * 16 + 8));
        float2 y0 = __ldg(reinterpret_cast<const float2*>(p2 + kt * 16));
        float2 y1 = __ldg(reinterpret_cast<const float2*>(p3 + kt * 16));
        float2 y2 = __ldg(reinterpret_cast<const float2*>(p2 + kt * 16 + 8));
        float2 y3 = __ldg(reinterpret_cast<const float2*>(p3 + kt * 16 + 8));

        uint32_t ahi0[4], alo0[4], ahi1[4], alo1[4];
        split2(x0, ahi0[0], alo0[0]);
        split2(x1, ahi0[1], alo0[1]);
        split2(x2, ahi0[2], alo0[2]);
        split2(x3, ahi0[3], alo0[3]);
        split2(y0, ahi1[0], alo1[0]);
        split2(y1, ahi1[1], alo1[1]);
        split2(y2, ahi1[2], alo1[2]);
        split2(y3, ahi1[3], alo1[3]);

        #pragma unroll
        for (int ntl = 0; ntl < 4; ntl++) {
            int ntg = cg * 4 + ntl;
            uint4 bb = __ldg(&g_wpk[(ntg * 8 + kt) * 32 + lane]);  // L1-hit after warmup
            mma_bf16(acc[0][ntl], ahi0, &bb.x);   // hi*hi
            mma_bf16(acc[1][ntl], ahi1, &bb.x);
            mma_bf16(acc[0][ntl], ahi0, &bb.z);   // hi*lo
            mma_bf16(acc[1][ntl], ahi1, &bb.z);
            mma_bf16(acc[0][ntl], alo0, &bb.x);   // lo*hi
            mma_bf16(acc[1][ntl], alo1, &bb.x);
        }
    }

    // ---- epilogue: bias + ssp + partial W2 dot over this warp's 32 cols ----
    float sum0 = 0.f, sum1 = 0.f, sum2 = 0.f, sum3 = 0.f;  // rows r0, r0+8, r0+16, r0+24
    const int tg2 = qc * 2;
    #pragma unroll
    for (int ntl = 0; ntl < 4; ntl++) {
        int c0 = (cg * 4 + ntl) * 8 + tg2;
        float2 b1v = __ldg(reinterpret_cast<const float2*>(b1 + c0));
        float2 w2v = __ldg(reinterpret_cast<const float2*>(W2 + c0));
        sum0 = fmaf(ssp(acc[0][ntl][0] + b1v.x), w2v.x, sum0);
        sum0 = fmaf(ssp(acc[0][ntl][1] + b1v.y), w2v.y, sum0);
        sum1 = fmaf(ssp(acc[0][ntl][2] + b1v.x), w2v.x, sum1);
        sum1 = fmaf(ssp(acc[0][ntl][3] + b1v.y), w2v.y, sum1);
        sum2 = fmaf(ssp(acc[1][ntl][0] + b1v.x), w2v.x, sum2);
        sum2 = fmaf(ssp(acc[1][ntl][1] + b1v.y), w2v.y, sum2);
        sum3 = fmaf(ssp(acc[1][ntl][2] + b1v.x), w2v.x, sum3);
        sum3 = fmaf(ssp(acc[1][ntl][3] + b1v.y), w2v.y, sum3);
    }
    // reduce over the 4 lanes of each quad (cols within the half)
    sum0 += __shfl_xor_sync(0xffffffffu, sum0, 1);
    sum0 += __shfl_xor_sync(0xffffffffu, sum0, 2);
    sum1 += __shfl_xor_sync(0xffffffffu, sum1, 1);
    sum1 += __shfl_xor_sync(0xffffffffu, sum1, 2);
    sum2 += __shfl_xor_sync(0xffffffffu, sum2, 1);
    sum2 += __shfl_xor_sync(0xffffffffu, sum2, 2);
    sum3 += __shfl_xor_sync(0xffffffffu, sum3, 1);
    sum3 += __shfl_xor_sync(0xffffffffu, sum3, 2);

    // per-row finish on quad leaders.  y_row = dot*std*mask + (b2*std+mean+aref)*mask;
    // this warp contributes dot_half*std*mask, and cg==0 adds the constant term.
    float contrib = 0.f;
    if (qc == 0) {
        float scStd = stddev[0];
        float s[4] = {sum0, sum1, sum2, sum3};
        float tot = 0.f;
        if (cg == 0) {
            float cbase = fmaf(b2[0], scStd, mean[0]);
            #pragma unroll
            for (int m = 0; m < 4; m++) {
                int g = b * NATOM + r0 + m * 8;
                float crow = cbase + atomref[atomic_numbers[g]];
                tot += fmaf(s[m], scStd, crow) * atom_mask[g];
            }
        } else {
            #pragma unroll
            for (int m = 0; m < 4; m++) {
                int g = b * NATOM + r0 + m * 8;
                tot += s[m] * scStd * atom_mask[g];
            }
        }
        contrib = tot;
    }
    // nonzero only at lanes ≡ 0 (mod 4): stages 4, 8, 16 suffice
    contrib += __shfl_xor_sync(0xffffffffu, contrib, 4);
    contrib += __shfl_xor_sync(0xffffffffu, contrib, 8);
    contrib += __shfl_xor_sync(0xffffffffu, contrib, 16);

    if (lane == 0) red[w] = contrib;
    __syncthreads();
    if (tid == 0) {
        float s = red[0];
        #pragma unroll
        for (int i = 1; i < 6; i++) s += red[i];
        out[b] = s;
    }
}

// ---------------- host launch ----------------
extern "C" void kernel_launch(void* const* d_in, const int* in_sizes, int n_in,
                              void* d_out, int out_size) {
    const float* rep   = (const float*)d_in[0];
    const int*   zn    = (const int*)  d_in[1];
    const float* mask  = (const float*)d_in[2];
    const float* W1    = (const float*)d_in[3];
    const float* b1    = (const float*)d_in[4];
    const float* W2    = (const float*)d_in[5];
    const float* b2    = (const float*)d_in[6];
    const float* aref  = (const float*)d_in[7];
    const float* mean  = (const float*)d_in[8];
    const float* stdd  = (const float*)d_in[9];
    float* out = (float*)d_out;

    prep_w_kernel<<<32, 256>>>(W1);
    atomwise_kernel<<<BATCH, 192>>>(rep, zn, mask, b1, W2, b2, aref, mean, stdd, out);
}

// round 8
// speedup vs baseline: 1.9317x; 1.4196x over previous
#include <cuda_runtime.h>
#include <cuda_fp16.h>
#include <cstdint>

// ---------------- problem constants ----------------
#define BATCH   2048
#define NATOM   96
#define NIN     128
#define NHID    64
#define SHIFTC  0.6931471805599453f

// ---------------- precomputed W1 fp16 image (B-fragment layout) ----------------
// uint2 index = (nt*8 + kt)*32 + lane ; .x = b0 (k pair, khalf 0), .y = b1 (khalf 1)
__device__ __align__(16) uint2 g_wh[2048];   // 16 KB, L1/L2-resident

// W1 is [NIN=128][NHID=64] row-major.  B fragment for mma.m16n8k16.row.col:
// lane = g*4+tg holds b0 = W[n=nt*8+g][k=kt*16+2tg+{0,1}], b1 = same n, k+8+{0,1}.
__global__ void prep_w_kernel(const float* __restrict__ W1) {
    int idx = blockIdx.x * blockDim.x + threadIdx.x;
    if (idx >= NIN * NHID) return;
    int k = idx >> 6;          // 0..127
    int n = idx & 63;          // 0..63
    __half h = __float2half_rn(W1[idx]);
    int nt = n >> 3, g = n & 7;
    int kt = k >> 4, kl = k & 15;
    int tg = (kl >> 1) & 3, br = kl >> 3, odd = kl & 1;
    uint32_t off = (uint32_t)((((nt * 8 + kt) * 32 + (g * 4 + tg)) * 8) + br * 4 + odd * 2);
    *reinterpret_cast<__half*>(reinterpret_cast<unsigned char*>(g_wh) + off) = h;
}

// ---------------- device helpers ----------------
__device__ __forceinline__ void mma_f16(float* c, const uint32_t* a, const uint32_t* b) {
    asm volatile(
        "mma.sync.aligned.m16n8k16.row.col.f32.f16.f16.f32 "
        "{%0,%1,%2,%3}, {%4,%5,%6,%7}, {%8,%9}, {%0,%1,%2,%3};"
        : "+f"(c[0]), "+f"(c[1]), "+f"(c[2]), "+f"(c[3])
        : "r"(a[0]), "r"(a[1]), "r"(a[2]), "r"(a[3]), "r"(b[0]), "r"(b[1]));
}

__device__ __forceinline__ float ssp(float z) {
    // shifted softplus, numerically stable
    return fmaxf(z, 0.f) + __logf(1.f + __expf(-fabsf(z))) - SHIFTC;
}

// hi/lo fp16 split of a float2 into packed half2 registers (x = xh + xl to ~2^-22)
__device__ __forceinline__ void split2h(float2 v, uint32_t& hi, uint32_t& lo) {
    __half2 h = __floats2half2_rn(v.x, v.y);
    float rx = v.x - __low2float(h);
    float ry = v.y - __high2float(h);
    __half2 l = __floats2half2_rn(rx, ry);
    hi = *reinterpret_cast<uint32_t*>(&h);
    lo = *reinterpret_cast<uint32_t*>(&l);
}

// ---------------- main fused kernel: one CTA (3 warps) per batch sample ----------------
// Warp w owns atom rows [32w, 32w+32) as TWO m16 tiles.  fp16 2-chain arithmetic:
// x·W = (xh + xl)·Wh  — x is exact in fp16 hi/lo, the only error is W's one-time fp16
// quantization (~2^-12 relative, analyzed final rel_err ~2e-4 vs 1e-3 gate).
// 2/3 the MMAs and 1/2 the B traffic of the bf16 3-chain.  A loads for kt+1 are
// issued between the split and the MMA block (1-stage register prefetch).
__global__ void __launch_bounds__(96, 4)
atomwise_kernel(const float* __restrict__ rep,
                const int*   __restrict__ atomic_numbers,
                const float* __restrict__ atom_mask,
                const float* __restrict__ b1,
                const float* __restrict__ W2,
                const float* __restrict__ b2,
                const float* __restrict__ atomref,
                const float* __restrict__ mean,
                const float* __restrict__ stddev,
                float*       __restrict__ out) {
    __shared__ float red[4];

    const int tid  = threadIdx.x;
    const int w    = tid >> 5;          // warp 0..2
    const int lane = tid & 31;
    const int b    = blockIdx.x;

    const int qr = lane >> 2;           // 0..7 (row group)
    const int qc = lane & 3;            // 0..3 (col pair)
    const int r0 = w * 32 + qr;         // rows r0, r0+8 (m-tile 0); r0+16, r0+24 (m-tile 1)

    const float* xb = rep + (size_t)b * (NATOM * NIN);
    const float* p0 = xb + (r0     ) * NIN + qc * 2;
    const float* p1 = xb + (r0 +  8) * NIN + qc * 2;
    const float* p2 = xb + (r0 + 16) * NIN + qc * 2;
    const float* p3 = xb + (r0 + 24) * NIN + qc * 2;

    float acc[2][8][4];
    #pragma unroll
    for (int m = 0; m < 2; m++)
        #pragma unroll
        for (int nt = 0; nt < 8; nt++)
            #pragma unroll
            for (int r = 0; r < 4; r++) acc[m][nt][r] = 0.f;

    // prefetch buffer: A fragments for the current kt (8 float2)
    float2 xf[8];
    xf[0] = __ldg(reinterpret_cast<const float2*>(p0));
    xf[1] = __ldg(reinterpret_cast<const float2*>(p1));
    xf[2] = __ldg(reinterpret_cast<const float2*>(p0 + 8));
    xf[3] = __ldg(reinterpret_cast<const float2*>(p1 + 8));
    xf[4] = __ldg(reinterpret_cast<const float2*>(p2));
    xf[5] = __ldg(reinterpret_cast<const float2*>(p3));
    xf[6] = __ldg(reinterpret_cast<const float2*>(p2 + 8));
    xf[7] = __ldg(reinterpret_cast<const float2*>(p3 + 8));

    #pragma unroll
    for (int kt = 0; kt < 8; kt++) {
        // split current A fragments to fp16 hi/lo
        uint32_t ahi0[4], alo0[4], ahi1[4], alo1[4];
        split2h(xf[0], ahi0[0], alo0[0]);
        split2h(xf[1], ahi0[1], alo0[1]);
        split2h(xf[2], ahi0[2], alo0[2]);
        split2h(xf[3], ahi0[3], alo0[3]);
        split2h(xf[4], ahi1[0], alo1[0]);
        split2h(xf[5], ahi1[1], alo1[1]);
        split2h(xf[6], ahi1[2], alo1[2]);
        split2h(xf[7], ahi1[3], alo1[3]);

        // issue next kt's A loads NOW — covered by the MMA block below
        if (kt < 7) {
            int o = (kt + 1) * 16;
            xf[0] = __ldg(reinterpret_cast<const float2*>(p0 + o));
            xf[1] = __ldg(reinterpret_cast<const float2*>(p1 + o));
            xf[2] = __ldg(reinterpret_cast<const float2*>(p0 + o + 8));
            xf[3] = __ldg(reinterpret_cast<const float2*>(p1 + o + 8));
            xf[4] = __ldg(reinterpret_cast<const float2*>(p2 + o));
            xf[5] = __ldg(reinterpret_cast<const float2*>(p3 + o));
            xf[6] = __ldg(reinterpret_cast<const float2*>(p2 + o + 8));
            xf[7] = __ldg(reinterpret_cast<const float2*>(p3 + o + 8));
        }

        #pragma unroll
        for (int nt = 0; nt < 8; nt++) {
            uint2 bb = __ldg(&g_wh[(nt * 8 + kt) * 32 + lane]);  // L1-hit after warmup
            // 2 chains x 2 m-tiles
            mma_f16(acc[0][nt], ahi0, &bb.x);   // xh * Wh
            mma_f16(acc[1][nt], ahi1, &bb.x);
            mma_f16(acc[0][nt], alo0, &bb.x);   // xl * Wh
            mma_f16(acc[1][nt], alo1, &bb.x);
        }
    }

    // ---- epilogue: bias + ssp + W2 dot, quad shuffle-reduce ----
    float sum0 = 0.f, sum1 = 0.f, sum2 = 0.f, sum3 = 0.f;  // rows r0, r0+8, r0+16, r0+24
    const int tg2 = qc * 2;
    #pragma unroll
    for (int nt = 0; nt < 8; nt++) {
        int c0 = nt * 8 + tg2;
        float2 b1v = __ldg(reinterpret_cast<const float2*>(b1 + c0));
        float2 w2v = __ldg(reinterpret_cast<const float2*>(W2 + c0));
        sum0 = fmaf(ssp(acc[0][nt][0] + b1v.x), w2v.x, sum0);
        sum0 = fmaf(ssp(acc[0][nt][1] + b1v.y), w2v.y, sum0);
        sum1 = fmaf(ssp(acc[0][nt][2] + b1v.x), w2v.x, sum1);
        sum1 = fmaf(ssp(acc[0][nt][3] + b1v.y), w2v.y, sum1);
        sum2 = fmaf(ssp(acc[1][nt][0] + b1v.x), w2v.x, sum2);
        sum2 = fmaf(ssp(acc[1][nt][1] + b1v.y), w2v.y, sum2);
        sum3 = fmaf(ssp(acc[1][nt][2] + b1v.x), w2v.x, sum3);
        sum3 = fmaf(ssp(acc[1][nt][3] + b1v.y), w2v.y, sum3);
    }
    // reduce over the 4 lanes of each quad (cols)
    sum0 += __shfl_xor_sync(0xffffffffu, sum0, 1);
    sum0 += __shfl_xor_sync(0xffffffffu, sum0, 2);
    sum1 += __shfl_xor_sync(0xffffffffu, sum1, 1);
    sum1 += __shfl_xor_sync(0xffffffffu, sum1, 2);
    sum2 += __shfl_xor_sync(0xffffffffu, sum2, 1);
    sum2 += __shfl_xor_sync(0xffffffffu, sum2, 2);
    sum3 += __shfl_xor_sync(0xffffffffu, sum3, 1);
    sum3 += __shfl_xor_sync(0xffffffffu, sum3, 2);

    // per-row finish on quad leaders, then warp-sum (deterministic)
    float contrib = 0.f;
    if (qc == 0) {
        float scB2 = b2[0], scMean = mean[0], scStd = stddev[0];
        float s[4] = {sum0, sum1, sum2, sum3};
        float tot = 0.f;
        #pragma unroll
        for (int m = 0; m < 4; m++) {
            int row = r0 + m * 8;
            int g = b * NATOM + row;
            float v = (s[m] + scB2) * scStd + scMean;
            v += atomref[atomic_numbers[g]];
            v *= atom_mask[g];
            tot += v;
        }
        contrib = tot;
    }
    // nonzero only at lanes ≡ 0 (mod 4): stages 4, 8, 16 suffice
    contrib += __shfl_xor_sync(0xffffffffu, contrib, 4);
    contrib += __shfl_xor_sync(0xffffffffu, contrib, 8);
    contrib += __shfl_xor_sync(0xffffffffu, contrib, 16);

    if (lane == 0) red[w] = contrib;
    __syncthreads();
    if (tid == 0) out[b] = red[0] + red[1] + red[2];
}

// ---------------- host launch ----------------
extern "C" void kernel_launch(void* const* d_in, const int* in_sizes, int n_in,
                              void* d_out, int out_size) {
    const float* rep   = (const float*)d_in[0];
    const int*   zn    = (const int*)  d_in[1];
    const float* mask  = (const float*)d_in[2];
    const float* W1    = (const float*)d_in[3];
    const float* b1    = (const float*)d_in[4];
    const float* W2    = (const float*)d_in[5];
    const float* b2    = (const float*)d_in[6];
    const float* aref  = (const float*)d_in[7];
    const float* mean  = (const float*)d_in[8];
    const float* stdd  = (const float*)d_in[9];
    float* out = (float*)d_out;

    prep_w_kernel<<<32, 256>>>(W1);
    atomwise_kernel<<<BATCH, 96>>>(rep, zn, mask, b1, W2, b2, aref, mean, stdd, out);
}